// round 3
// baseline (speedup 1.0000x reference)
#include <cuda_runtime.h>
#include <cuda_bf16.h>
#include <cstdint>

// TensorDLT closed-form solve for fixed source corners
// (0,0),(127,0),(127,127),(0,127). 8 fp32 in -> 9 fp32 out per element.
//
//   h2 = u1', h5 = v1'
//   a_i = (u_i'-u1')/127, c_i = (v1'-v_i')/127
//   2x2:  (u2'-u3') h6 + (u4'-u3') h7 = a3-a2-a4
//         (v3'-v2') h6 + (v3'-v4') h7 = c3-c2-c4
//   h0 = u2' h6 + a2, h1 = u4' h7 + a4, h3 = v2' h6 - c2, h4 = v4' h7 - c4
//
// R3: input via coalesced LDG.128; output staged in SMEM (stride-9 STS,
// conflict-free) and flushed with ONE cp.async.bulk (TMA bulk store) per
// block — removes the LDS+STG readback loop from the SM issue path.

#define BLOCK 256

__device__ __forceinline__ uint32_t smem_u32(const void* p) {
    uint32_t a;
    asm("{ .reg .u64 t; cvta.to.shared.u64 t, %1; cvt.u32.u64 %0, t; }"
        : "=r"(a) : "l"(p));
    return a;
}

__global__ void __launch_bounds__(BLOCK) tensor_dlt_kernel(
    const float* __restrict__ offset,  // [B, 8]
    float* __restrict__ out,           // [B, 9]
    int B)
{
    __shared__ __align__(16) float s[BLOCK * 9];

    const int base = blockIdx.x * BLOCK;
    const int b = base + threadIdx.x;

    if (b < B) {
        const float4* p = reinterpret_cast<const float4*>(offset) + (size_t)b * 2;
        const float4 o0 = p[0];
        const float4 o1 = p[1];

        const float up1 =   0.0f + 32.0f * o0.x;
        const float vp1 =   0.0f + 32.0f * o0.y;
        const float up2 = 127.0f + 32.0f * o0.z;
        const float vp2 =   0.0f + 32.0f * o0.w;
        const float up3 = 127.0f + 32.0f * o1.x;
        const float vp3 = 127.0f + 32.0f * o1.y;
        const float up4 =   0.0f + 32.0f * o1.z;
        const float vp4 = 127.0f + 32.0f * o1.w;

        const float inv127 = 1.0f / 127.0f;
        const float a2 = (up2 - up1) * inv127;
        const float a3 = (up3 - up1) * inv127;
        const float a4 = (up4 - up1) * inv127;
        const float c2 = (vp1 - vp2) * inv127;
        const float c3 = (vp1 - vp3) * inv127;
        const float c4 = (vp1 - vp4) * inv127;

        const float m00 = up2 - up3;
        const float m01 = up4 - up3;
        const float m10 = vp3 - vp2;
        const float m11 = vp3 - vp4;
        const float r0 = a3 - a2 - a4;
        const float r1 = c3 - c2 - c4;

        const float invdet = 1.0f / (m00 * m11 - m01 * m10);
        const float h6 = (r0 * m11 - m01 * r1) * invdet;
        const float h7 = (m00 * r1 - r0 * m10) * invdet;

        // stride-9 SMEM rows: gcd(9,32)=1 -> bank-conflict-free
        float* row = s + threadIdx.x * 9;
        row[0] = up2 * h6 + a2;
        row[1] = up4 * h7 + a4;
        row[2] = up1;
        row[3] = vp2 * h6 - c2;
        row[4] = vp4 * h7 - c4;
        row[5] = vp1;
        row[6] = h6;
        row[7] = h7;
        row[8] = 1.0f;
    }
    __syncthreads();

    const int valid = min(BLOCK, B - base);
    float* dst = out + (size_t)base * 9;

    if (valid == BLOCK) {
        // One async bulk store per block: 256*9*4 = 9216 B, 16B-aligned
        // (dst offset = 9216 * blockIdx.x).
        if (threadIdx.x == 0) {
            asm volatile("fence.proxy.async.shared::cta;" ::: "memory");
            const uint32_t src = smem_u32(s);
            asm volatile(
                "cp.async.bulk.global.shared::cta.bulk_group [%0], [%1], %2;"
                :: "l"(dst), "r"(src), "n"(BLOCK * 9 * 4)
                : "memory");
            asm volatile("cp.async.bulk.commit_group;" ::: "memory");
            // Must complete before CTA exit frees SMEM.
            asm volatile("cp.async.bulk.wait_group.read 0;" ::: "memory");
        }
    } else {
        const int n = valid * 9;
        for (int i = threadIdx.x; i < n; i += BLOCK)
            dst[i] = s[i];
    }
}

extern "C" void kernel_launch(void* const* d_in, const int* in_sizes, int n_in,
                              void* d_out, int out_size)
{
    const float* offset = (const float*)d_in[0];
    float* out = (float*)d_out;
    const int B = in_sizes[0] / 8;
    const int grid = (B + BLOCK - 1) / BLOCK;
    tensor_dlt_kernel<<<grid, BLOCK>>>(offset, out, B);
}